// round 2
// baseline (speedup 1.0000x reference)
#include <cuda_runtime.h>

#define N_NODES   100000
#define N_EDGES   800000
#define N_ETYPES  5
#define IN_DIM    23
#define AGG_PAD   24
#define HID_DIM   128
#define OUT_DIM   64
#define NUM_GRAPHS 64

// ---------------- scratch (device globals; no allocation allowed) ----------
__device__ unsigned int g_deg[N_ETYPES * N_NODES];                  // 2 MB
__device__ float g_inv[N_ETYPES * N_NODES];                         // 2 MB
__device__ float g_agg1[(size_t)N_ETYPES * N_NODES * AGG_PAD];      // 48 MB
__device__ float g_h1[(size_t)N_NODES * HID_DIM];                   // 51.2 MB
__device__ float g_S[N_ETYPES * NUM_GRAPHS * HID_DIM];              // 160 KB
__device__ int   g_gstart[NUM_GRAPHS + 1];

// ---------------- kernel 1: deg + 23-dim feature scatter -------------------
// warp handles 32 consecutive edges of one etype.
__global__ void k_scatter1(const int* __restrict__ src, const int* __restrict__ dst,
                           const float* __restrict__ feat) {
    int wg   = (blockIdx.x * blockDim.x + threadIdx.x) >> 5;
    int lane = threadIdx.x & 31;
    const int warps_per_e = N_EDGES / 32;          // 25000 (exact)
    int e    = wg / warps_per_e;
    int base = (wg % warps_per_e) * 32;
    const int* se = src + (size_t)e * N_EDGES;
    const int* de = dst + (size_t)e * N_EDGES;
    int s32 = se[base + lane];
    int d32 = de[base + lane];
    atomicAdd(&g_deg[e * N_NODES + d32], 1u);
    float* agge = g_agg1 + (size_t)e * N_NODES * AGG_PAD;
#pragma unroll 1
    for (int k = 0; k < 32; k++) {
        int s = __shfl_sync(0xffffffffu, s32, k);
        int d = __shfl_sync(0xffffffffu, d32, k);
        if (lane < IN_DIM) {
            float v = __ldg(&feat[(size_t)s * IN_DIM + lane]);
            atomicAdd(&agge[(size_t)d * AGG_PAD + lane], v);
        }
    }
}

// ---------------- kernel 2: inv = 1/(deg+1) --------------------------------
__global__ void k_inv() {
    int i = blockIdx.x * blockDim.x + threadIdx.x;
    if (i < N_ETYPES * N_NODES) g_inv[i] = 1.0f / (float)(g_deg[i] + 1u);
}

// ---------------- kernel 3: graph boundaries (graph_ids is sorted) ---------
__global__ void k_bounds(const int* __restrict__ gid) {
    int i = blockIdx.x * blockDim.x + threadIdx.x;
    if (i >= N_NODES) return;
    int g = gid[i];
    if (i == 0) {
        for (int q = 0; q <= g; q++) g_gstart[q] = 0;
    } else {
        int gp = gid[i - 1];
        for (int q = gp + 1; q <= g; q++) g_gstart[q] = i;
    }
    if (i == N_NODES - 1) {
        for (int q = g + 1; q <= NUM_GRAPHS; q++) g_gstart[q] = N_NODES;
    }
}

// ---------------- kernel 4: layer-1 node projection ------------------------
// h1[i] = relu( sum_e ((agg1_e[i]+feat[i]) * inv_e[i]) @ W1_e + sum_e b1_e )
// W1 (58.9KB) + combined b1 in dynamic shared. Warp processes 4 nodes; lane
// owns out-dims {lane, lane+32, lane+64, lane+96}.
__global__ void k_layer1(const float* __restrict__ feat,
                         const float* __restrict__ W1, const float* __restrict__ b1) {
    extern __shared__ float dsh[];
    float* Wsh = dsh;                                   // 5*23*128
    float* b1s = dsh + N_ETYPES * IN_DIM * HID_DIM;     // 128
    for (int t = threadIdx.x; t < N_ETYPES * IN_DIM * HID_DIM; t += blockDim.x)
        Wsh[t] = W1[t];
    for (int t = threadIdx.x; t < HID_DIM; t += blockDim.x) {
        float s = 0.f;
#pragma unroll
        for (int e = 0; e < N_ETYPES; e++) s += b1[e * HID_DIM + t];
        b1s[t] = s;
    }
    __syncthreads();

    int lane = threadIdx.x & 31;
    int warp = (blockIdx.x * blockDim.x + threadIdx.x) >> 5;
    int base = warp * 4;
    if (base >= N_NODES) return;

    float y[4][N_ETYPES];
#pragma unroll
    for (int j = 0; j < 4; j++) {
        int i = base + j;
        bool val = (i < N_NODES);
        float invr = 0.f;
        if (val && lane < N_ETYPES) invr = g_inv[lane * N_NODES + i];
        float f = 0.f;
        if (val && lane < IN_DIM) f = feat[(size_t)i * IN_DIM + lane];
#pragma unroll
        for (int e = 0; e < N_ETYPES; e++) {
            float a = 0.f;
            if (val && lane < IN_DIM)
                a = g_agg1[((size_t)e * N_NODES + i) * AGG_PAD + lane];
            float iv = __shfl_sync(0xffffffffu, invr, e);
            y[j][e] = (a + f) * iv;
        }
    }

    float acc[4][4];
#pragma unroll
    for (int j = 0; j < 4; j++)
#pragma unroll
        for (int c = 0; c < 4; c++) acc[j][c] = b1s[lane + 32 * c];

#pragma unroll
    for (int e = 0; e < N_ETYPES; e++) {
        const float* We = Wsh + e * IN_DIM * HID_DIM + lane;
        float ye0 = y[0][e], ye1 = y[1][e], ye2 = y[2][e], ye3 = y[3][e];
#pragma unroll 1
        for (int k = 0; k < IN_DIM; k++) {
            float x0 = __shfl_sync(0xffffffffu, ye0, k);
            float x1 = __shfl_sync(0xffffffffu, ye1, k);
            float x2 = __shfl_sync(0xffffffffu, ye2, k);
            float x3 = __shfl_sync(0xffffffffu, ye3, k);
            const float* wp = We + k * HID_DIM;
#pragma unroll
            for (int c = 0; c < 4; c++) {
                float w = wp[32 * c];
                acc[0][c] = fmaf(x0, w, acc[0][c]);
                acc[1][c] = fmaf(x1, w, acc[1][c]);
                acc[2][c] = fmaf(x2, w, acc[2][c]);
                acc[3][c] = fmaf(x3, w, acc[3][c]);
            }
        }
    }

#pragma unroll
    for (int j = 0; j < 4; j++) {
        int i = base + j;
        if (i < N_NODES) {
#pragma unroll
            for (int c = 0; c < 4; c++)
                g_h1[((size_t)i << 7) + lane + 32 * c] = fmaxf(acc[j][c], 0.f);
        }
    }
}

// ---------------- kernel 5: layer-2 edge pass into S -----------------------
// S_e[g][t] += sum over edges (s->d) in E_e with gid(d)=g of h1[s][t]*inv_e[d].
// Atomic-free shared accumulator: thread t exclusively owns column t.
#define EB   8192
#define TILE 128
__global__ void k_layer2edge(const int* __restrict__ src, const int* __restrict__ dst,
                             const int* __restrict__ gid) {
    __shared__ float acc[NUM_GRAPHS * HID_DIM];   // 32 KB
    __shared__ int2  sed[TILE];                    // packed {src|g<<20, inv}
    const int bpe = (N_EDGES + EB - 1) / EB;       // 98
    int e      = blockIdx.x / bpe;
    int estart = (blockIdx.x % bpe) * EB;
    int ecount = min(EB, N_EDGES - estart);
    const int* se = src + (size_t)e * N_EDGES + estart;
    const int* de = dst + (size_t)e * N_EDGES + estart;
    int t = threadIdx.x;                           // dim 0..127

    for (int q = t; q < NUM_GRAPHS * HID_DIM; q += blockDim.x) acc[q] = 0.f;
    __syncthreads();

    for (int tb = 0; tb < ecount; tb += TILE) {
        int n = min(TILE, ecount - tb);
        if (t < n) {
            int s = se[tb + t];
            int d = de[tb + t];
            int g = gid[d];
            float v = g_inv[e * N_NODES + d];
            sed[t] = make_int2(s | (g << 20), __float_as_int(v));
        }
        __syncthreads();
#pragma unroll 4
        for (int j = 0; j < n; j++) {
            int2 p  = sed[j];
            int  s  = p.x & 0xFFFFF;
            int  g  = p.x >> 20;
            float v = __int_as_float(p.y);
            acc[(g << 7) + t] += g_h1[((size_t)s << 7) + t] * v;
        }
        __syncthreads();
    }

    float* Se = g_S + e * NUM_GRAPHS * HID_DIM;
    for (int g = 0; g < NUM_GRAPHS; g++) {
        float v = acc[(g << 7) + t];
        if (v != 0.f) atomicAdd(&Se[(g << 7) + t], v);
    }
}

// ---------------- kernel 6: layer-2 self term ------------------------------
// S_e[gid(i)][t] += h1[i][t] * inv_e[i], exploiting sorted gid for register acc.
#define CHUNK 1024
__global__ void k_self(const int* __restrict__ gid) {
    int start = blockIdx.x * CHUNK;
    int end   = min(start + CHUNK, N_NODES);
    int t = threadIdx.x;
    float acc[N_ETYPES] = {0.f, 0.f, 0.f, 0.f, 0.f};
    int gcur = gid[start];
    for (int i = start; i < end; i++) {
        int g = gid[i];
        if (g != gcur) {
#pragma unroll
            for (int e = 0; e < N_ETYPES; e++) {
                if (acc[e] != 0.f)
                    atomicAdd(&g_S[(e * NUM_GRAPHS + gcur) * HID_DIM + t], acc[e]);
                acc[e] = 0.f;
            }
            gcur = g;
        }
        float h = g_h1[((size_t)i << 7) + t];
#pragma unroll
        for (int e = 0; e < N_ETYPES; e++)
            acc[e] += h * g_inv[e * N_NODES + i];
    }
#pragma unroll
    for (int e = 0; e < N_ETYPES; e++)
        if (acc[e] != 0.f)
            atomicAdd(&g_S[(e * NUM_GRAPHS + gcur) * HID_DIM + t], acc[e]);
}

// ---------------- kernel 7: finisher ---------------------------------------
// out[g][o] = (sum_e S_e[g] @ W2_e)[o] / max(N_g,1) + sum_e b2_e[o]
__global__ void k_final(const float* __restrict__ W2, const float* __restrict__ b2,
                        float* __restrict__ out) {
    int g = blockIdx.x;
    int o = threadIdx.x;
    __shared__ float Ss[HID_DIM];
    float a = 0.f;
    for (int e = 0; e < N_ETYPES; e++) {
        __syncthreads();
        for (int q = o; q < HID_DIM; q += blockDim.x)
            Ss[q] = g_S[(e * NUM_GRAPHS + g) * HID_DIM + q];
        __syncthreads();
        const float* We = W2 + (size_t)e * HID_DIM * OUT_DIM;
#pragma unroll 4
        for (int k = 0; k < HID_DIM; k++)
            a = fmaf(Ss[k], We[k * OUT_DIM + o], a);
    }
    int cnt = g_gstart[g + 1] - g_gstart[g];
    float bsum = 0.f;
#pragma unroll
    for (int e = 0; e < N_ETYPES; e++) bsum += b2[e * OUT_DIM + o];
    out[g * OUT_DIM + o] = (cnt > 0) ? (a / (float)cnt + bsum) : 0.f;
}

// ---------------- launcher --------------------------------------------------
extern "C" void kernel_launch(void* const* d_in, const int* in_sizes, int n_in,
                              void* d_out, int out_size) {
    const float* feat = (const float*)d_in[0];
    const int*   src  = (const int*)  d_in[1];
    const int*   dst  = (const int*)  d_in[2];
    const int*   gid  = (const int*)  d_in[3];
    const float* W1   = (const float*)d_in[4];
    const float* b1   = (const float*)d_in[5];
    const float* W2   = (const float*)d_in[6];
    const float* b2   = (const float*)d_in[7];
    float* out = (float*)d_out;

    void *p_deg, *p_agg1, *p_S;
    cudaGetSymbolAddress(&p_deg,  g_deg);
    cudaGetSymbolAddress(&p_agg1, g_agg1);
    cudaGetSymbolAddress(&p_S,    g_S);
    cudaMemsetAsync(p_deg,  0, sizeof(unsigned int) * N_ETYPES * N_NODES, 0);
    cudaMemsetAsync(p_agg1, 0, sizeof(float) * (size_t)N_ETYPES * N_NODES * AGG_PAD, 0);
    cudaMemsetAsync(p_S,    0, sizeof(float) * N_ETYPES * NUM_GRAPHS * HID_DIM, 0);

    // deg + feature scatter: 5*800000 edges, warp per 32 edges
    k_scatter1<<<(N_ETYPES * (N_EDGES / 32)) / 8, 256>>>(src, dst, feat);
    k_inv<<<(N_ETYPES * N_NODES + 255) / 256, 256>>>();
    k_bounds<<<(N_NODES + 255) / 256, 256>>>(gid);

    size_t shmem = (size_t)(N_ETYPES * IN_DIM * HID_DIM + HID_DIM) * sizeof(float); // 59392
    cudaFuncSetAttribute(k_layer1, cudaFuncAttributeMaxDynamicSharedMemorySize, (int)shmem);
    // 8 warps/block * 4 nodes/warp = 32 nodes per block -> 3125 blocks
    k_layer1<<<(N_NODES + 31) / 32, 256, shmem>>>(feat, W1, b1);

    k_layer2edge<<<N_ETYPES * ((N_EDGES + EB - 1) / EB), TILE>>>(src, dst, gid);
    k_self<<<(N_NODES + CHUNK - 1) / CHUNK, HID_DIM>>>(gid);
    k_final<<<NUM_GRAPHS, OUT_DIM>>>(W2, b2, out);
}